// round 14
// baseline (speedup 1.0000x reference)
#include <cuda_runtime.h>
#include <stdint.h>
#include <math.h>

#define Bt 4
#define Tt 2048
#define Dd 1024
#define Ee 8
#define Ff 2752
#define TOPK 2
#define Ntok (Bt*Tt)        // 8192 tokens
#define NR   (Ntok*TOPK)    // 16384 routed rows

// ======================= device scratch (static, no allocs) =======================
// fp32 arrays holding tf32-rounded values; k-dim quad-interleaved per 16-group:
// position of k-local i (0..31): (i&16) + ((i&3)<<2) + ((i&15)>>2)
// => thread tig's four k's {tig, tig+4, tig+8, tig+12} are 16B-contiguous.
__device__ float g_x32[(size_t)Ntok * Dd];          // x, perm'd over D
__device__ float g_wg32[(size_t)Ee * Ff * Dd];      // [e][n(F)][k(D) perm]
__device__ float g_wu32[(size_t)Ee * Ff * Dd];
__device__ float g_wd32[(size_t)Ee * Dd * Ff];      // [e][n(D)][k(F) perm]
__device__ float g_h32[(size_t)NR * Ff];            // h, perm'd over F
__device__ float g_y[(size_t)NR * Dd];
__device__ int   g_row_token[NR];
__device__ int   g_pos[Ntok * TOPK];
__device__ int   g_tok_eid[Ntok * TOPK];
__device__ float g_tok_w[Ntok * TOPK];
__device__ int   g_counts[Ee];
__device__ int   g_offs[Ee + 1];
__device__ int   g_cursor[Ee];
__device__ int   g_tile_off[Ee + 1];
__device__ float g_load[Ee];

// ======================= helpers =======================
__device__ __forceinline__ uint32_t smem_u32(const void* p) {
    uint32_t a;
    asm("{ .reg .u64 t; cvta.to.shared.u64 t, %1; cvt.u32.u64 %0, t; }" : "=r"(a) : "l"(p));
    return a;
}
__device__ __forceinline__ float rna_tf32(float v) {
    uint32_t r;
    asm("cvt.rna.tf32.f32 %0, %1;" : "=r"(r) : "f"(v));
    return __uint_as_float(r);
}
__device__ __forceinline__ int perm32(int i) {
    return (i & 16) + ((i & 3) << 2) + ((i & 15) >> 2);
}

#define CPASYNC(dst, src) \
    asm volatile("cp.async.cg.shared.global [%0], [%1], 16;" :: "r"(dst), "l"(src) : "memory")
#define CPCOMMIT() asm volatile("cp.async.commit_group;" ::: "memory")
#define CPWAIT1()  asm volatile("cp.async.wait_group 1;" ::: "memory")
#define CPWAIT0()  asm volatile("cp.async.wait_group 0;" ::: "memory")

#define LDS128(r, a) \
    asm volatile("ld.shared.v4.b32 {%0,%1,%2,%3}, [%4];" \
        : "=r"((r)[0]), "=r"((r)[1]), "=r"((r)[2]), "=r"((r)[3]) : "r"(a))

#define MMA_TF32(c, a, b) \
    asm volatile("mma.sync.aligned.m16n8k8.row.col.f32.tf32.tf32.f32 " \
        "{%0,%1,%2,%3}, {%4,%5,%6,%7}, {%8,%9}, {%0,%1,%2,%3};" \
        : "+f"((c)[0]), "+f"((c)[1]), "+f"((c)[2]), "+f"((c)[3]) \
        : "r"((a)[0]), "r"((a)[1]), "r"((a)[2]), "r"((a)[3]), "r"((b)[0]), "r"((b)[1]))

// smem row: 32 floats (BK=32 slice, quad-perm'd) = 128B payload, padded to 192B.
// 192B = 48 words; 48 mod 32 = 16 => within a v4 quarter-warp phase, the two grp rows
// map to banks 0-15 / 16-31 respectively: conflict-free LDS128.
#define RSTR 192
#define A_TILE_B (128 * RSTR)        // 24576
#define B1_TILE_B (64 * RSTR)        // 12288 (gemm1 per matrix)
#define STAGE 49152                  // gemm1: A + Bg + Bu ; gemm2: A + Bd(128*192)
#define SMEM_TOT (2 * STAGE + 512)

// ======================= pass 0: zero metadata =======================
__global__ void __launch_bounds__(32) zero_meta_kernel() {
    int t = threadIdx.x;
    if (t < Ee) { g_counts[t] = 0; g_load[t] = 0.0f; }
}

// ======================= gating + x -> tf32 perm (fused; exact fp32 routing) ==============
__global__ void __launch_bounds__(128) gate_kernel(const float* __restrict__ x,
                                                   const float* __restrict__ gw) {
    int warp = (blockIdx.x * blockDim.x + threadIdx.x) >> 5;
    int lane = threadIdx.x & 31;
    if (warp >= Ntok) return;
    const float* xr = x + (size_t)warp * Dd;
    float xv[32];
#pragma unroll
    for (int j = 0; j < 32; j++) xv[j] = xr[j * 32 + lane];

    int pl = perm32(lane);
#pragma unroll
    for (int j = 0; j < 32; j++)
        g_x32[(size_t)warp * Dd + j * 32 + pl] = rna_tf32(xv[j]);

    float p[Ee];
#pragma unroll
    for (int e = 0; e < Ee; e++) {
        float s = 0.0f;
#pragma unroll
        for (int j = 0; j < 32; j++) s += xv[j] * gw[(j * 32 + lane) * Ee + e];
#pragma unroll
        for (int o = 16; o; o >>= 1) s += __shfl_xor_sync(0xffffffffu, s, o);
        p[e] = s;
    }
    float mx = p[0];
#pragma unroll
    for (int e = 1; e < Ee; e++) mx = fmaxf(mx, p[e]);
    float den = 0.0f;
#pragma unroll
    for (int e = 0; e < Ee; e++) { p[e] = expf(p[e] - mx); den += p[e]; }
    float inv = 1.0f / den;
#pragma unroll
    for (int e = 0; e < Ee; e++) p[e] *= inv;
    int i1 = 0;
#pragma unroll
    for (int e = 1; e < Ee; e++) if (p[e] > p[i1]) i1 = e;
    int i2 = -1; float b2 = -1.0f;
#pragma unroll
    for (int e = 0; e < Ee; e++) {
        if (e == i1) continue;
        if (p[e] > b2) { b2 = p[e]; i2 = e; }
    }
    float s2 = p[i1] + p[i2] + 1e-8f;
    if (lane == 0) {
        g_tok_eid[warp * 2 + 0] = i1;
        g_tok_eid[warp * 2 + 1] = i2;
        g_tok_w[warp * 2 + 0] = p[i1] / s2;
        g_tok_w[warp * 2 + 1] = p[i2] / s2;
        atomicAdd(&g_counts[i1], 1);
        atomicAdd(&g_counts[i2], 1);
#pragma unroll
        for (int e = 0; e < Ee; e++) atomicAdd(&g_load[e], p[e]);
    }
}

// ======================= scan / build =======================
__global__ void __launch_bounds__(32) scan_kernel() {
    if (threadIdx.x != 0) return;
    int s = 0, ts = 0;
    for (int e = 0; e < Ee; e++) {
        g_offs[e] = s; g_cursor[e] = s; g_tile_off[e] = ts;
        ts += (g_counts[e] + 127) / 128;
        s += g_counts[e];
    }
    g_offs[Ee] = s; g_tile_off[Ee] = ts;
}

__global__ void __launch_bounds__(256) build_kernel() {
    int t = blockIdx.x * blockDim.x + threadIdx.x;
    if (t >= Ntok) return;
#pragma unroll
    for (int k = 0; k < TOPK; k++) {
        int e = g_tok_eid[t * 2 + k];
        int r = atomicAdd(&g_cursor[e], 1);
        g_row_token[r] = t;
        g_pos[t * 2 + k] = r;
    }
}

// ======================= prep: transpose + tf32 round + k-perm =======================
__global__ void __launch_bounds__(256) wprep_gu_kernel(const float* __restrict__ wg,
                                                       const float* __restrict__ wu) {
    __shared__ float t[32][33];
    int z = blockIdx.z;
    int e = z & 7;
    const float* src = (z < Ee ? wg : wu);
    float* dst = (z < Ee ? g_wg32 : g_wu32);
    size_t base = (size_t)e * Dd * Ff;
    int n0 = blockIdx.x * 32, k0 = blockIdx.y * 32;
#pragma unroll
    for (int i = 0; i < 4; i++) {
        int k = k0 + threadIdx.y + i * 8;
        t[threadIdx.y + i * 8][threadIdx.x] = src[base + (size_t)k * Ff + n0 + threadIdx.x];
    }
    __syncthreads();
    int tx = threadIdx.x;
    int pk = k0 + perm32(tx);
#pragma unroll
    for (int i = 0; i < 4; i++) {
        int n = n0 + threadIdx.y + i * 8;
        float v = t[tx][threadIdx.y + i * 8];
        dst[base + (size_t)n * Dd + pk] = rna_tf32(v);
    }
}

__global__ void __launch_bounds__(256) wprep_d_kernel(const float* __restrict__ wd) {
    __shared__ float t[32][33];
    int e = blockIdx.z;
    size_t base = (size_t)e * Ff * Dd;
    int n0 = blockIdx.x * 32, k0 = blockIdx.y * 32;
#pragma unroll
    for (int i = 0; i < 4; i++) {
        int k = k0 + threadIdx.y + i * 8;
        t[threadIdx.y + i * 8][threadIdx.x] = wd[base + (size_t)k * Dd + n0 + threadIdx.x];
    }
    __syncthreads();
    int tx = threadIdx.x;
    int pk = k0 + perm32(tx);
#pragma unroll
    for (int i = 0; i < 4; i++) {
        int n = n0 + threadIdx.y + i * 8;
        float v = t[tx][threadIdx.y + i * 8];
        g_wd32[base + (size_t)n * Ff + pk] = rna_tf32(v);
    }
}

// ======================= gemm1: h = silu(X Wg) * (X Wu), tf32, LDS128 frags ==============
extern "C" __global__ void __launch_bounds__(256, 2)
gemm1_mma_kernel() {
    extern __shared__ __align__(16) char smem[];
    int tid = threadIdx.x, wid = tid >> 5, lane = tid & 31;
    int grp = lane >> 2, tig = lane & 3;

    int bid = blockIdx.y * 43 + blockIdx.x;
    int group = bid / (43 * 8);
    int within = bid - group * (43 * 8);
    int j = group * 8 + (within & 7);
    int nt = within >> 3;

    if (j >= g_tile_off[Ee]) return;
    int e = 0;
#pragma unroll
    for (int q = 0; q < Ee - 1; q++) if (j >= g_tile_off[q + 1]) e = q + 1;
    int mt0 = j - g_tile_off[e];
    int rowStart = g_offs[e] + mt0 * 128;
    int end = g_offs[e + 1];
    int n0 = nt * 64;

    uint32_t sb = smem_u32(smem);
    int* tokS = (int*)(smem + 2 * STAGE);
    if (tid < 128) {
        int rr = rowStart + tid; if (rr > end - 1) rr = end - 1;
        tokS[tid] = g_row_token[rr];
    }
    __syncthreads();

    const float* wg32 = g_wg32 + ((size_t)e * Ff + n0) * Dd;
    const float* wu32 = g_wu32 + ((size_t)e * Ff + n0) * Dd;

    float cg[2][4][4] = {}, cu[2][4][4] = {};
    const int NIT = Dd / 32;   // 32

    int mwbase = (wid & 3) * 32;
    int nwbase = (wid >> 2) * 32;

    auto issue = [&](int it) {
        uint32_t stu = sb + (it & 1) * STAGE;
        int k0 = it * 32;
#pragma unroll
        for (int q = 0; q < 8; q++) {
            int c = tid + q * 256;
            if (c < 1024) {                     // A: 128 rows * 8 chunks (16B)
                int row = c >> 3, ck = c & 7;
                const float* src = g_x32 + (size_t)tokS[row] * Dd + k0 + ck * 4;
                CPASYNC(stu + row * RSTR + ck * 16, src);
            } else {                            // B: 2 mats * 64 rows * 8 chunks
                int b = c - 1024, mat = b >> 9, idx = b & 511, row = idx >> 3, ck = idx & 7;
                const float* src = (mat ? wu32 : wg32) + (size_t)row * Dd + k0 + ck * 4;
                CPASYNC(stu + A_TILE_B + mat * B1_TILE_B + row * RSTR + ck * 16, src);
            }
        }
        CPCOMMIT();
    };

    issue(0);
    for (int it = 0; it < NIT; it++) {
        if (it + 1 < NIT) { issue(it + 1); CPWAIT1(); } else { CPWAIT0(); }
        __syncthreads();
        uint32_t stu = sb + (it & 1) * STAGE;
#pragma unroll
        for (int kp2 = 0; kp2 < 2; kp2++) {
            uint32_t alo[2][4], ahi[2][4];     // [mt]: rows grp, grp+8; regs = k tig,+4,+8,+12
#pragma unroll
            for (int mt = 0; mt < 2; mt++) {
                uint32_t ab = stu + (mwbase + mt * 16 + grp) * RSTR + kp2 * 64 + tig * 16;
                LDS128(alo[mt], ab);
                LDS128(ahi[mt], ab + 8 * RSTR);
            }
#pragma unroll
            for (int n8 = 0; n8 < 4; n8++) {
                uint32_t badr = stu + A_TILE_B + (nwbase + n8 * 8 + grp) * RSTR + kp2 * 64 + tig * 16;
                uint32_t bg[4], bu[4];
                LDS128(bg, badr);
                LDS128(bu, badr + B1_TILE_B);
#pragma unroll
                for (int kk = 0; kk < 2; kk++) {
                    uint32_t bfg[2] = {bg[2 * kk], bg[2 * kk + 1]};
                    uint32_t bfu[2] = {bu[2 * kk], bu[2 * kk + 1]};
#pragma unroll
                    for (int mt = 0; mt < 2; mt++) {
                        uint32_t af[4] = {alo[mt][2 * kk], ahi[mt][2 * kk],
                                          alo[mt][2 * kk + 1], ahi[mt][2 * kk + 1]};
                        MMA_TF32(cg[mt][n8], af, bfg);
                        MMA_TF32(cu[mt][n8], af, bfu);
                    }
                }
            }
        }
        __syncthreads();
    }

    // epilogue: SwiGLU, tf32-round, store h (perm'd over F)
#pragma unroll
    for (int mt = 0; mt < 2; mt++) {
#pragma unroll
        for (int half = 0; half < 2; half++) {
            int row = rowStart + mwbase + mt * 16 + grp + half * 8;
            if (row >= end) continue;
#pragma unroll
            for (int n8 = 0; n8 < 4; n8++) {
                int c = n0 + nwbase + n8 * 8 + tig * 2;   // F index (even)
                float g0 = cg[mt][n8][half * 2], g1 = cg[mt][n8][half * 2 + 1];
                float u0 = cu[mt][n8][half * 2], u1 = cu[mt][n8][half * 2 + 1];
                float z0 = g0 / (1.0f + expf(-g0)) * u0;
                float z1 = g1 / (1.0f + expf(-g1)) * u1;
                int p0 = (c & ~31) + perm32(c & 31);
                int p1 = ((c + 1) & ~31) + perm32((c + 1) & 31);
                g_h32[(size_t)row * Ff + p0] = rna_tf32(z0);
                g_h32[(size_t)row * Ff + p1] = rna_tf32(z1);
            }
        }
    }
}

// ======================= gemm2: y = h @ Wd, tf32, LDS128 frags =======================
extern "C" __global__ void __launch_bounds__(256, 2)
gemm2_mma_kernel() {
    extern __shared__ __align__(16) char smem[];
    int tid = threadIdx.x, wid = tid >> 5, lane = tid & 31;
    int grp = lane >> 2, tig = lane & 3;

    int bid = blockIdx.y * 8 + blockIdx.x;
    int group = bid / (17 * 8);
    int within = bid - group * (17 * 8);
    int j = group * 17 + (within % 17);
    int nt = within / 17;

    if (j >= g_tile_off[Ee]) return;
    int e = 0;
#pragma unroll
    for (int q = 0; q < Ee - 1; q++) if (j >= g_tile_off[q + 1]) e = q + 1;
    int mt0 = j - g_tile_off[e];
    int rowStart = g_offs[e] + mt0 * 128;
    int end = g_offs[e + 1];
    int n0 = nt * 128;

    uint32_t sb = smem_u32(smem);
    const float* wd32 = g_wd32 + ((size_t)e * Dd + n0) * Ff;

    float cc_[2][8][4] = {};
    const int NIT = Ff / 32;    // 86

    int mwbase = (wid & 3) * 32;
    int nwbase = (wid >> 2) * 64;

    auto issue = [&](int it) {
        uint32_t stu = sb + (it & 1) * STAGE;
        int k0 = it * 32;
#pragma unroll
        for (int q = 0; q < 8; q++) {
            int c = tid + q * 256;
            if (c < 1024) {                     // A (h): 128 rows * 8 chunks
                int row = c >> 3, ck = c & 7;
                int rr = rowStart + row; if (rr > end - 1) rr = end - 1;
                const float* src = g_h32 + (size_t)rr * Ff + k0 + ck * 4;
                CPASYNC(stu + row * RSTR + ck * 16, src);
            } else {                            // B (wd): 128 rows * 8 chunks
                int idx = c - 1024, row = idx >> 3, ck = idx & 7;
                const float* src = wd32 + (size_t)row * Ff + k0 + ck * 4;
                CPASYNC(stu + A_TILE_B + row * RSTR + ck * 16, src);
            }
        }
        CPCOMMIT();
    };

    issue(0);
    for (int it = 0; it < NIT; it++) {
        if (it + 1 < NIT) { issue(it + 1); CPWAIT1(); } else { CPWAIT0(); }
        __syncthreads();
        uint32_t stu = sb + (it & 1) * STAGE;
#pragma unroll
        for (int kp2 = 0; kp2 < 2; kp2++) {
            uint32_t alo[2][4], ahi[2][4];
#pragma unroll
            for (int mt = 0; mt < 2; mt++) {
                uint32_t ab = stu + (mwbase + mt * 16 + grp) * RSTR + kp2 * 64 + tig * 16;
                LDS128(alo[mt], ab);
                LDS128(ahi[mt], ab + 8 * RSTR);
            }
#pragma unroll
            for (int n8 = 0; n8 < 8; n8++) {
                uint32_t badr = stu + A_TILE_B + (nwbase + n8 * 8 + grp) * RSTR + kp2 * 64 + tig * 16;
                uint32_t bv[4];
                LDS128(bv, badr);
#pragma unroll
                for (int kk = 0; kk < 2; kk++) {
                    uint32_t bf[2] = {bv[2 * kk], bv[2 * kk + 1]};
#pragma unroll
                    for (int mt = 0; mt < 2; mt++) {
                        uint32_t af[4] = {alo[mt][2 * kk], ahi[mt][2 * kk],
                                          alo[mt][2 * kk + 1], ahi[mt][2 * kk + 1]};
                        MMA_TF32(cc_[mt][n8], af, bf);
                    }
                }
            }
        }
        __syncthreads();
    }

#pragma unroll
    for (int mt = 0; mt < 2; mt++) {
#pragma unroll
        for (int half = 0; half < 2; half++) {
            int row = rowStart + mwbase + mt * 16 + grp + half * 8;
            if (row >= end) continue;
#pragma unroll
            for (int n8 = 0; n8 < 8; n8++) {
                int col = n0 + nwbase + n8 * 8 + tig * 2;
                float2 v = make_float2(cc_[mt][n8][half * 2], cc_[mt][n8][half * 2 + 1]);
                *(float2*)(g_y + (size_t)row * Dd + col) = v;
            }
        }
    }
}

// ======================= combine =======================
__global__ void __launch_bounds__(256) combine_kernel(float* __restrict__ out) {
    const int nq = Ntok * (Dd / 4);
    for (int idx = blockIdx.x * blockDim.x + threadIdx.x; idx < nq;
         idx += gridDim.x * blockDim.x) {
        int t = idx / (Dd / 4);
        int dq = idx - t * (Dd / 4);
        int p0 = g_pos[t * 2 + 0], p1 = g_pos[t * 2 + 1];
        float w0 = g_tok_w[t * 2 + 0], w1 = g_tok_w[t * 2 + 1];
        float4 a = *(const float4*)(g_y + (size_t)p0 * Dd + dq * 4);
        float4 b = *(const float4*)(g_y + (size_t)p1 * Dd + dq * 4);
        float4 o;
        o.x = w0 * a.x + w1 * b.x;
        o.y = w0 * a.y + w1 * b.y;
        o.z = w0 * a.z + w1 * b.z;
        o.w = w0 * a.w + w1 * b.w;
        *(float4*)(out + (size_t)t * Dd + dq * 4) = o;
    }
}

// ======================= aux loss =======================
__global__ void __launch_bounds__(32) aux_kernel(float* __restrict__ out, int out_size) {
    if (threadIdx.x != 0 || blockIdx.x != 0) return;
    float s = 0.0f;
    for (int e = 0; e < Ee; e++) {
        float load = g_load[e] / (float)Ntok;
        float frac = (float)g_counts[e] / (float)(Ntok * TOPK);
        s += frac * load;
    }
    float aux = 0.01f * (float)Ee * s;
    for (int i = Ntok * Dd; i < out_size; i++) out[i] = aux;
}

// ======================= launch =======================
extern "C" void kernel_launch(void* const* d_in, const int* in_sizes, int n_in,
                              void* d_out, int out_size) {
    const float* x      = (const float*)d_in[0];
    const float* gate_w = (const float*)d_in[1];
    const float* w_gate = (const float*)d_in[2];
    const float* w_up   = (const float*)d_in[3];
    const float* w_down = (const float*)d_in[4];
    float* out = (float*)d_out;

    cudaFuncSetAttribute(gemm1_mma_kernel, cudaFuncAttributeMaxDynamicSharedMemorySize, SMEM_TOT);
    cudaFuncSetAttribute(gemm2_mma_kernel, cudaFuncAttributeMaxDynamicSharedMemorySize, SMEM_TOT);

    dim3 tb(32, 8);
    zero_meta_kernel<<<1, 32>>>();                                // 1
    gate_kernel<<<Ntok / 4, 128>>>(x, gate_w);                    // 2 (also x->tf32 perm)
    scan_kernel<<<1, 32>>>();                                     // 3
    build_kernel<<<(Ntok + 255) / 256, 256>>>();                  // 4
    wprep_gu_kernel<<<dim3(Ff / 32, Dd / 32, 16), tb>>>(w_gate, w_up);  // 5
    gemm1_mma_kernel<<<dim3(43, 136), 256, SMEM_TOT>>>();         // 6
    wprep_d_kernel<<<dim3(Dd / 32, Ff / 32, Ee), tb>>>(w_down);   // 7
    gemm2_mma_kernel<<<dim3(8, 136), 256, SMEM_TOT>>>();          // 8
    combine_kernel<<<1184, 256>>>(out);                           // 9
    aux_kernel<<<1, 32>>>(out, out_size);                         // 10
}

// round 15
// speedup vs baseline: 1.8541x; 1.8541x over previous
#include <cuda_runtime.h>
#include <stdint.h>
#include <math.h>

#define Bt 4
#define Tt 2048
#define Dd 1024
#define Ee 8
#define Ff 2752
#define TOPK 2
#define Ntok (Bt*Tt)        // 8192 tokens
#define NR   (Ntok*TOPK)    // 16384 routed rows

// ======================= device scratch (static, no allocs) =======================
// fp32 arrays holding tf32-rounded values; k-dim stored pair-interleaved per 8-group:
// pos 2j <- k=j ; pos 2j+1 <- k=j+4  (j=0..3)
__device__ float g_x32[(size_t)Ntok * Dd];          // x, perm'd over D
__device__ float g_wg32[(size_t)Ee * Ff * Dd];      // [e][n(F)][k(D) perm]
__device__ float g_wu32[(size_t)Ee * Ff * Dd];
__device__ float g_wd32[(size_t)Ee * Dd * Ff];      // [e][n(D)][k(F) perm]
__device__ float g_h32[(size_t)NR * Ff];            // h, perm'd over F
__device__ float g_y[(size_t)NR * Dd];
__device__ int   g_row_token[NR];
__device__ int   g_pos[Ntok * TOPK];
__device__ int   g_tok_eid[Ntok * TOPK];
__device__ float g_tok_w[Ntok * TOPK];
__device__ int   g_counts[Ee];
__device__ int   g_offs[Ee + 1];
__device__ int   g_cursor[Ee];
__device__ int   g_tile_off[Ee + 1];
__device__ float g_load[Ee];

// ======================= helpers =======================
__device__ __forceinline__ uint32_t smem_u32(const void* p) {
    uint32_t a;
    asm("{ .reg .u64 t; cvta.to.shared.u64 t, %1; cvt.u32.u64 %0, t; }" : "=r"(a) : "l"(p));
    return a;
}
__device__ __forceinline__ float rna_tf32(float v) {
    uint32_t r;
    asm("cvt.rna.tf32.f32 %0, %1;" : "=r"(r) : "f"(v));
    return __uint_as_float(r);
}
__device__ __forceinline__ int perm8(int i) {
    return (i & 4) ? (2 * (i & 3) + 1) : (2 * (i & 3));
}

#define CPASYNC(dst, src) \
    asm volatile("cp.async.cg.shared.global [%0], [%1], 16;" :: "r"(dst), "l"(src) : "memory")
#define CPCOMMIT() asm volatile("cp.async.commit_group;" ::: "memory")
#define CPWAIT1()  asm volatile("cp.async.wait_group 1;" ::: "memory")
#define CPWAIT0()  asm volatile("cp.async.wait_group 0;" ::: "memory")

#define LDS64(lo, hi, a) \
    asm volatile("ld.shared.v2.b32 {%0,%1}, [%2];" : "=r"(lo), "=r"(hi) : "r"(a))

#define MMA_TF32(c, a, b) \
    asm volatile("mma.sync.aligned.m16n8k8.row.col.f32.tf32.tf32.f32 " \
        "{%0,%1,%2,%3}, {%4,%5,%6,%7}, {%8,%9}, {%0,%1,%2,%3};" \
        : "+f"((c)[0]), "+f"((c)[1]), "+f"((c)[2]), "+f"((c)[3]) \
        : "r"((a)[0]), "r"((a)[1]), "r"((a)[2]), "r"((a)[3]), "r"((b)[0]), "r"((b)[1]))

// smem row: 32 floats = 128B payload, padded to 160B (40 words).
// LDS64 at row*160 + kp*32 + tig*8 -> (k=tig, k=tig+4); half-warp phase banks
// 8*grp + 2*tig (+1) cover all 32 banks: conflict-free.
#define RSTR 160
#define A_TILE_B (128 * RSTR)        // 20480
#define B1_TILE_B (64 * RSTR)        // 10240
#define STAGE 40960
#define SMEM_TOT (2 * STAGE + 512)

// ======================= pass 0: zero metadata =======================
__global__ void __launch_bounds__(32) zero_meta_kernel() {
    int t = threadIdx.x;
    if (t < Ee) { g_counts[t] = 0; g_load[t] = 0.0f; }
}

// ======================= gating + x -> tf32 perm (fused; exact fp32 routing) ==============
__global__ void __launch_bounds__(128) gate_kernel(const float* __restrict__ x,
                                                   const float* __restrict__ gw) {
    int warp = (blockIdx.x * blockDim.x + threadIdx.x) >> 5;
    int lane = threadIdx.x & 31;
    if (warp >= Ntok) return;
    const float* xr = x + (size_t)warp * Dd;
    float xv[32];
#pragma unroll
    for (int j = 0; j < 32; j++) xv[j] = xr[j * 32 + lane];

    int pl = (lane & ~7) + perm8(lane & 7);
#pragma unroll
    for (int j = 0; j < 32; j++)
        g_x32[(size_t)warp * Dd + j * 32 + pl] = rna_tf32(xv[j]);

    float p[Ee];
#pragma unroll
    for (int e = 0; e < Ee; e++) {
        float s = 0.0f;
#pragma unroll
        for (int j = 0; j < 32; j++) s += xv[j] * gw[(j * 32 + lane) * Ee + e];
#pragma unroll
        for (int o = 16; o; o >>= 1) s += __shfl_xor_sync(0xffffffffu, s, o);
        p[e] = s;
    }
    float mx = p[0];
#pragma unroll
    for (int e = 1; e < Ee; e++) mx = fmaxf(mx, p[e]);
    float den = 0.0f;
#pragma unroll
    for (int e = 0; e < Ee; e++) { p[e] = expf(p[e] - mx); den += p[e]; }
    float inv = 1.0f / den;
#pragma unroll
    for (int e = 0; e < Ee; e++) p[e] *= inv;
    int i1 = 0;
#pragma unroll
    for (int e = 1; e < Ee; e++) if (p[e] > p[i1]) i1 = e;
    int i2 = -1; float b2 = -1.0f;
#pragma unroll
    for (int e = 0; e < Ee; e++) {
        if (e == i1) continue;
        if (p[e] > b2) { b2 = p[e]; i2 = e; }
    }
    float s2 = p[i1] + p[i2] + 1e-8f;
    if (lane == 0) {
        g_tok_eid[warp * 2 + 0] = i1;
        g_tok_eid[warp * 2 + 1] = i2;
        g_tok_w[warp * 2 + 0] = p[i1] / s2;
        g_tok_w[warp * 2 + 1] = p[i2] / s2;
        atomicAdd(&g_counts[i1], 1);
        atomicAdd(&g_counts[i2], 1);
#pragma unroll
        for (int e = 0; e < Ee; e++) atomicAdd(&g_load[e], p[e]);
    }
}

// ======================= scan / build =======================
__global__ void __launch_bounds__(32) scan_kernel() {
    if (threadIdx.x != 0) return;
    int s = 0, ts = 0;
    for (int e = 0; e < Ee; e++) {
        g_offs[e] = s; g_cursor[e] = s; g_tile_off[e] = ts;
        ts += (g_counts[e] + 127) / 128;
        s += g_counts[e];
    }
    g_offs[Ee] = s; g_tile_off[Ee] = ts;
}

__global__ void __launch_bounds__(256) build_kernel() {
    int t = blockIdx.x * blockDim.x + threadIdx.x;
    if (t >= Ntok) return;
#pragma unroll
    for (int k = 0; k < TOPK; k++) {
        int e = g_tok_eid[t * 2 + k];
        int r = atomicAdd(&g_cursor[e], 1);
        g_row_token[r] = t;
        g_pos[t * 2 + k] = r;
    }
}

// ======================= prep: transpose + tf32 round + k-perm =======================
__global__ void __launch_bounds__(256) wprep_gu_kernel(const float* __restrict__ wg,
                                                       const float* __restrict__ wu) {
    __shared__ float t[32][33];
    int z = blockIdx.z;
    int e = z & 7;
    const float* src = (z < Ee ? wg : wu);
    float* dst = (z < Ee ? g_wg32 : g_wu32);
    size_t base = (size_t)e * Dd * Ff;
    int n0 = blockIdx.x * 32, k0 = blockIdx.y * 32;
#pragma unroll
    for (int i = 0; i < 4; i++) {
        int k = k0 + threadIdx.y + i * 8;
        t[threadIdx.y + i * 8][threadIdx.x] = src[base + (size_t)k * Ff + n0 + threadIdx.x];
    }
    __syncthreads();
    int tx = threadIdx.x;
    int pk = k0 + (tx & ~7) + perm8(tx & 7);
#pragma unroll
    for (int i = 0; i < 4; i++) {
        int n = n0 + threadIdx.y + i * 8;
        float v = t[tx][threadIdx.y + i * 8];
        dst[base + (size_t)n * Dd + pk] = rna_tf32(v);
    }
}

__global__ void __launch_bounds__(256) wprep_d_kernel(const float* __restrict__ wd) {
    __shared__ float t[32][33];
    int e = blockIdx.z;
    size_t base = (size_t)e * Ff * Dd;
    int n0 = blockIdx.x * 32, k0 = blockIdx.y * 32;
#pragma unroll
    for (int i = 0; i < 4; i++) {
        int k = k0 + threadIdx.y + i * 8;
        t[threadIdx.y + i * 8][threadIdx.x] = wd[base + (size_t)k * Dd + n0 + threadIdx.x];
    }
    __syncthreads();
    int tx = threadIdx.x;
    int pk = k0 + (tx & ~7) + perm8(tx & 7);
#pragma unroll
    for (int i = 0; i < 4; i++) {
        int n = n0 + threadIdx.y + i * 8;
        float v = t[tx][threadIdx.y + i * 8];
        g_wd32[base + (size_t)n * Ff + pk] = rna_tf32(v);
    }
}

// ======================= gemm1: h = silu(X Wg) * (X Wu), tf32 single-pass ==============
extern "C" __global__ void __launch_bounds__(256, 2)
gemm1_mma_kernel() {
    extern __shared__ __align__(16) char smem[];
    int tid = threadIdx.x, wid = tid >> 5, lane = tid & 31;
    int grp = lane >> 2, tig = lane & 3;

    int bid = blockIdx.y * 43 + blockIdx.x;
    int group = bid / (43 * 8);
    int within = bid - group * (43 * 8);
    int j = group * 8 + (within & 7);
    int nt = within >> 3;

    if (j >= g_tile_off[Ee]) return;
    int e = 0;
#pragma unroll
    for (int q = 0; q < Ee - 1; q++) if (j >= g_tile_off[q + 1]) e = q + 1;
    int mt0 = j - g_tile_off[e];
    int rowStart = g_offs[e] + mt0 * 128;
    int end = g_offs[e + 1];
    int n0 = nt * 64;

    uint32_t sb = smem_u32(smem);
    int* tokS = (int*)(smem + 2 * STAGE);
    if (tid < 128) {
        int rr = rowStart + tid; if (rr > end - 1) rr = end - 1;
        tokS[tid] = g_row_token[rr];
    }
    __syncthreads();

    const float* wg32 = g_wg32 + ((size_t)e * Ff + n0) * Dd;
    const float* wu32 = g_wu32 + ((size_t)e * Ff + n0) * Dd;

    float cg[2][4][4] = {}, cu[2][4][4] = {};
    const int NIT = Dd / 32;   // 32

    int mwbase = (wid & 3) * 32;
    int nwbase = (wid >> 2) * 32;

    auto issue = [&](int it) {
        uint32_t stu = sb + (it & 1) * STAGE;
        int k0 = it * 32;
#pragma unroll
        for (int q = 0; q < 8; q++) {
            int c = tid + q * 256;
            if (c < 1024) {                     // A: 128 rows * 8 chunks (16B)
                int row = c >> 3, ck = c & 7;
                const float* src = g_x32 + (size_t)tokS[row] * Dd + k0 + ck * 4;
                CPASYNC(stu + row * RSTR + ck * 16, src);
            } else {                            // B: 2 mats * 64 rows * 8 chunks
                int b = c - 1024, mat = b >> 9, idx = b & 511, row = idx >> 3, ck = idx & 7;
                const float* src = (mat ? wu32 : wg32) + (size_t)row * Dd + k0 + ck * 4;
                CPASYNC(stu + A_TILE_B + mat * B1_TILE_B + row * RSTR + ck * 16, src);
            }
        }
        CPCOMMIT();
    };

    issue(0);
    for (int it = 0; it < NIT; it++) {
        if (it + 1 < NIT) { issue(it + 1); CPWAIT1(); } else { CPWAIT0(); }
        __syncthreads();
        uint32_t stu = sb + (it & 1) * STAGE;
#pragma unroll
        for (int kp = 0; kp < 4; kp++) {
            uint32_t a[2][4];
#pragma unroll
            for (int mt = 0; mt < 2; mt++) {
                uint32_t ab = stu + (mwbase + mt * 16 + grp) * RSTR + kp * 32 + tig * 8;
                LDS64(a[mt][0], a[mt][2], ab);               // row grp:   (k=tig, k=tig+4)
                LDS64(a[mt][1], a[mt][3], ab + 8 * RSTR);    // row grp+8
            }
#pragma unroll
            for (int n8 = 0; n8 < 4; n8++) {
                uint32_t badr = stu + A_TILE_B + (nwbase + n8 * 8 + grp) * RSTR + kp * 32 + tig * 8;
                uint32_t bg[2], bu[2];
                LDS64(bg[0], bg[1], badr);
                LDS64(bu[0], bu[1], badr + B1_TILE_B);
#pragma unroll
                for (int mt = 0; mt < 2; mt++) {
                    MMA_TF32(cg[mt][n8], a[mt], bg);
                    MMA_TF32(cu[mt][n8], a[mt], bu);
                }
            }
        }
        __syncthreads();
    }

    // epilogue: SwiGLU, tf32-round, store h (perm'd over F)
#pragma unroll
    for (int mt = 0; mt < 2; mt++) {
#pragma unroll
        for (int half = 0; half < 2; half++) {
            int row = rowStart + mwbase + mt * 16 + grp + half * 8;
            if (row >= end) continue;
#pragma unroll
            for (int n8 = 0; n8 < 4; n8++) {
                int c = n0 + nwbase + n8 * 8 + tig * 2;   // F index (even)
                float g0 = cg[mt][n8][half * 2], g1 = cg[mt][n8][half * 2 + 1];
                float u0 = cu[mt][n8][half * 2], u1 = cu[mt][n8][half * 2 + 1];
                float z0 = g0 / (1.0f + expf(-g0)) * u0;
                float z1 = g1 / (1.0f + expf(-g1)) * u1;
                int p0 = (c & ~7) + perm8(c & 7);
                int p1 = ((c + 1) & ~7) + perm8((c + 1) & 7);
                g_h32[(size_t)row * Ff + p0] = rna_tf32(z0);
                g_h32[(size_t)row * Ff + p1] = rna_tf32(z1);
            }
        }
    }
}

// ======================= gemm2: y = h @ Wd, tf32 single-pass =======================
extern "C" __global__ void __launch_bounds__(256, 2)
gemm2_mma_kernel() {
    extern __shared__ __align__(16) char smem[];
    int tid = threadIdx.x, wid = tid >> 5, lane = tid & 31;
    int grp = lane >> 2, tig = lane & 3;

    int bid = blockIdx.y * 8 + blockIdx.x;
    int group = bid / (17 * 8);
    int within = bid - group * (17 * 8);
    int j = group * 17 + (within % 17);
    int nt = within / 17;

    if (j >= g_tile_off[Ee]) return;
    int e = 0;
#pragma unroll
    for (int q = 0; q < Ee - 1; q++) if (j >= g_tile_off[q + 1]) e = q + 1;
    int mt0 = j - g_tile_off[e];
    int rowStart = g_offs[e] + mt0 * 128;
    int end = g_offs[e + 1];
    int n0 = nt * 128;

    uint32_t sb = smem_u32(smem);
    const float* wd32 = g_wd32 + ((size_t)e * Dd + n0) * Ff;

    float cc_[2][8][4] = {};
    const int NIT = Ff / 32;    // 86

    int mwbase = (wid & 3) * 32;
    int nwbase = (wid >> 2) * 64;

    auto issue = [&](int it) {
        uint32_t stu = sb + (it & 1) * STAGE;
        int k0 = it * 32;
#pragma unroll
        for (int q = 0; q < 8; q++) {
            int c = tid + q * 256;
            if (c < 1024) {                     // A (h): 128 rows * 8 chunks
                int row = c >> 3, ck = c & 7;
                int rr = rowStart + row; if (rr > end - 1) rr = end - 1;
                const float* src = g_h32 + (size_t)rr * Ff + k0 + ck * 4;
                CPASYNC(stu + row * RSTR + ck * 16, src);
            } else {                            // B (wd): 128 rows * 8 chunks
                int idx = c - 1024, row = idx >> 3, ck = idx & 7;
                const float* src = wd32 + (size_t)row * Ff + k0 + ck * 4;
                CPASYNC(stu + A_TILE_B + row * RSTR + ck * 16, src);
            }
        }
        CPCOMMIT();
    };

    issue(0);
    for (int it = 0; it < NIT; it++) {
        if (it + 1 < NIT) { issue(it + 1); CPWAIT1(); } else { CPWAIT0(); }
        __syncthreads();
        uint32_t stu = sb + (it & 1) * STAGE;
#pragma unroll
        for (int kp = 0; kp < 4; kp++) {
            uint32_t a[2][4];
#pragma unroll
            for (int mt = 0; mt < 2; mt++) {
                uint32_t ab = stu + (mwbase + mt * 16 + grp) * RSTR + kp * 32 + tig * 8;
                LDS64(a[mt][0], a[mt][2], ab);
                LDS64(a[mt][1], a[mt][3], ab + 8 * RSTR);
            }
#pragma unroll
            for (int n8 = 0; n8 < 8; n8++) {
                uint32_t badr = stu + A_TILE_B + (nwbase + n8 * 8 + grp) * RSTR + kp * 32 + tig * 8;
                uint32_t b[2];
                LDS64(b[0], b[1], badr);
#pragma unroll
                for (int mt = 0; mt < 2; mt++) {
                    MMA_TF32(cc_[mt][n8], a[mt], b);
                }
            }
        }
        __syncthreads();
    }

#pragma unroll
    for (int mt = 0; mt < 2; mt++) {
#pragma unroll
        for (int half = 0; half < 2; half++) {
            int row = rowStart + mwbase + mt * 16 + grp + half * 8;
            if (row >= end) continue;
#pragma unroll
            for (int n8 = 0; n8 < 8; n8++) {
                int col = n0 + nwbase + n8 * 8 + tig * 2;
                float2 v = make_float2(cc_[mt][n8][half * 2], cc_[mt][n8][half * 2 + 1]);
                *(float2*)(g_y + (size_t)row * Dd + col) = v;
            }
        }
    }
}

// ======================= combine + aux (fused) =======================
__global__ void __launch_bounds__(256) combine_kernel(float* __restrict__ out, int out_size) {
    if (blockIdx.x == 0 && threadIdx.x == 0) {
        float s = 0.0f;
        for (int e = 0; e < Ee; e++) {
            float load = g_load[e] / (float)Ntok;
            float frac = (float)g_counts[e] / (float)(Ntok * TOPK);
            s += frac * load;
        }
        float aux = 0.01f * (float)Ee * s;
        for (int i = Ntok * Dd; i < out_size; i++) out[i] = aux;
    }
    const int nq = Ntok * (Dd / 4);
    for (int idx = blockIdx.x * blockDim.x + threadIdx.x; idx < nq;
         idx += gridDim.x * blockDim.x) {
        int t = idx / (Dd / 4);
        int dq = idx - t * (Dd / 4);
        int p0 = g_pos[t * 2 + 0], p1 = g_pos[t * 2 + 1];
        float w0 = g_tok_w[t * 2 + 0], w1 = g_tok_w[t * 2 + 1];
        float4 a = *(const float4*)(g_y + (size_t)p0 * Dd + dq * 4);
        float4 b = *(const float4*)(g_y + (size_t)p1 * Dd + dq * 4);
        float4 o;
        o.x = w0 * a.x + w1 * b.x;
        o.y = w0 * a.y + w1 * b.y;
        o.z = w0 * a.z + w1 * b.z;
        o.w = w0 * a.w + w1 * b.w;
        *(float4*)(out + (size_t)t * Dd + dq * 4) = o;
    }
}

// ======================= launch =======================
extern "C" void kernel_launch(void* const* d_in, const int* in_sizes, int n_in,
                              void* d_out, int out_size) {
    const float* x      = (const float*)d_in[0];
    const float* gate_w = (const float*)d_in[1];
    const float* w_gate = (const float*)d_in[2];
    const float* w_up   = (const float*)d_in[3];
    const float* w_down = (const float*)d_in[4];
    float* out = (float*)d_out;

    cudaFuncSetAttribute(gemm1_mma_kernel, cudaFuncAttributeMaxDynamicSharedMemorySize, SMEM_TOT);
    cudaFuncSetAttribute(gemm2_mma_kernel, cudaFuncAttributeMaxDynamicSharedMemorySize, SMEM_TOT);

    dim3 tb(32, 8);
    zero_meta_kernel<<<1, 32>>>();                                // 1
    gate_kernel<<<Ntok / 4, 128>>>(x, gate_w);                    // 2 (also x->tf32 perm)
    scan_kernel<<<1, 32>>>();                                     // 3
    build_kernel<<<(Ntok + 255) / 256, 256>>>();                  // 4
    wprep_gu_kernel<<<dim3(Ff / 32, Dd / 32, 16), tb>>>(w_gate, w_up);  // 5
    gemm1_mma_kernel<<<dim3(43, 136), 256, SMEM_TOT>>>();         // 6
    wprep_d_kernel<<<dim3(Dd / 32, Ff / 32, Ee), tb>>>(w_down);   // 7
    gemm2_mma_kernel<<<dim3(8, 136), 256, SMEM_TOT>>>();          // 8
    combine_kernel<<<1184, 256>>>(out, out_size);                 // 9 (aux fused)
}